// round 4
// baseline (speedup 1.0000x reference)
#include <cuda_runtime.h>
#include <math.h>
#include <stdint.h>

#define B_N 4096
#define D_N 16384

// W_FIRST = 2 - 10 * (2/49), W_LAST = 2 - W_FIRST, batch_step = (W_FIRST-W_LAST)/(B-1)
#define EPOCH_STEP (2.0 / 49.0)
#define W_FIRST_D  (2.0 - 10.0 * EPOCH_STEP)   /* ~1.5918367346938775 */
#define W_LAST_D   (2.0 - W_FIRST_D)
#define BATCH_STEP_D ((W_FIRST_D - W_LAST_D) / (double)(B_N - 1))

// Sortable keys: (float_bits << 12) | row_index.
// difficulty > 0 always, so the raw IEEE bit pattern is order-preserving.
// Low 12 bits = index -> exact stable-argsort tie-break in one u64 '<'.
__device__ __align__(16) unsigned long long g_keys[B_N];

// ---------------------------------------------------------------------------
// Kernel 1: difficulty[i] = 0.5*loss[i] + 0.5*||gradients[i,:]||_2
// One block per row, 256 threads, fully unrolled float4 loads (16 in flight).
// Writes difficulty to out[1+i] AND the sortable key to g_keys[i].
// Block 0 zeroes the weighted-loss accumulator out[0].
// ---------------------------------------------------------------------------
__global__ __launch_bounds__(256) void difficulty_kernel(
    const float* __restrict__ loss,
    const float4* __restrict__ grad,       // [B, D/4]
    float* __restrict__ out)               // out[0]=acc, out[1..B]=difficulty
{
    const int row = blockIdx.x;
    const int tid = threadIdx.x;

    if (row == 0 && tid == 0) out[0] = 0.0f;   // reset accumulator (graph replay safe)

    const float4* __restrict__ g = grad + (size_t)row * (D_N / 4);

    float s = 0.0f;
#pragma unroll
    for (int it = 0; it < 16; it++) {          // 16 independent LDG.128 in flight
        float4 v = g[tid + it * 256];
        s = fmaf(v.x, v.x, s);
        s = fmaf(v.y, v.y, s);
        s = fmaf(v.z, v.z, s);
        s = fmaf(v.w, v.w, s);
    }

    // warp reduce
#pragma unroll
    for (int off = 16; off > 0; off >>= 1)
        s += __shfl_xor_sync(0xFFFFFFFFu, s, off);

    __shared__ float warp_sums[8];
    if ((tid & 31) == 0) warp_sums[tid >> 5] = s;
    __syncthreads();

    if (tid == 0) {
        float tot = 0.0f;
#pragma unroll
        for (int w = 0; w < 8; w++) tot += warp_sums[w];
        float d = 0.5f * loss[row] + 0.5f * sqrtf(tot);
        out[1 + row] = d;
        g_keys[row] = ((unsigned long long)__float_as_uint(d) << 12) | (unsigned)row;
    }
}

// ---------------------------------------------------------------------------
// Kernel 2: counting rank + weighted loss accumulation.
// Each block owns 4 consecutive i's; 256 threads scan all B keys as uint4
// (2 u64 keys per 16B load), fully unrolled: 8 independent LDG.128 in flight,
// each load reused for 4 i-compares.
// rank(i) = #{ key_j < key_i }  (exact stable-argsort rank via packed index)
// One atomicAdd per block into out[0].
// ---------------------------------------------------------------------------
#define IPB 4       // i's per block
#define K2_THREADS 256
#define K2_ITERS (B_N / 2 / K2_THREADS)   // 8 uint4 loads per thread

__global__ __launch_bounds__(K2_THREADS) void rank_weight_kernel(
    const float* __restrict__ loss,
    float* __restrict__ out)
{
    const int i0  = blockIdx.x * IPB;
    const int tid = threadIdx.x;

    unsigned long long ki[IPB];
#pragma unroll
    for (int k = 0; k < IPB; k++) ki[k] = g_keys[i0 + k];

    const uint4* __restrict__ keys4 = (const uint4*)g_keys;  // 2 keys per uint4

    // Issue all loads up front (8 independent LDG.128 in flight)
    uint4 v[K2_ITERS];
#pragma unroll
    for (int it = 0; it < K2_ITERS; it++)
        v[it] = keys4[tid + it * K2_THREADS];

    int cnt[IPB] = {0, 0, 0, 0};
#pragma unroll
    for (int it = 0; it < K2_ITERS; it++) {
        unsigned long long k0 = ((unsigned long long)v[it].y << 32) | v[it].x;
        unsigned long long k1 = ((unsigned long long)v[it].w << 32) | v[it].z;
#pragma unroll
        for (int k = 0; k < IPB; k++) {
            cnt[k] += (k0 < ki[k]);
            cnt[k] += (k1 < ki[k]);
        }
    }

    // warp reduce all 4 counters
#pragma unroll
    for (int off = 16; off > 0; off >>= 1) {
#pragma unroll
        for (int k = 0; k < IPB; k++)
            cnt[k] += __shfl_xor_sync(0xFFFFFFFFu, cnt[k], off);
    }

    __shared__ int warp_cnt[K2_THREADS / 32][IPB];
    if ((tid & 31) == 0) {
#pragma unroll
        for (int k = 0; k < IPB; k++)
            warp_cnt[tid >> 5][k] = cnt[k];
    }
    __syncthreads();

    if (tid == 0) {
        float contrib = 0.0f;
#pragma unroll
        for (int k = 0; k < IPB; k++) {
            int rank = 0;
#pragma unroll
            for (int w = 0; w < K2_THREADS / 32; w++) rank += warp_cnt[w][k];
            float wgt = (float)(W_FIRST_D - BATCH_STEP_D * (double)rank);
            contrib += __ldg(&loss[i0 + k]) * wgt;
        }
        atomicAdd(&out[0], contrib * (1.0f / (float)B_N));
    }
}

// ---------------------------------------------------------------------------
extern "C" void kernel_launch(void* const* d_in, const int* in_sizes, int n_in,
                              void* d_out, int out_size)
{
    const float*  loss = (const float*)d_in[0];
    const float4* grad = (const float4*)d_in[1];
    float* out = (float*)d_out;

    difficulty_kernel<<<B_N, 256>>>(loss, grad, out);
    rank_weight_kernel<<<B_N / IPB, K2_THREADS>>>(loss, out);
}

// round 5
// speedup vs baseline: 1.0421x; 1.0421x over previous
#include <cuda_runtime.h>
#include <math.h>
#include <stdint.h>

#define B_N 4096
#define D_N 16384

// W_FIRST = 2 - 10 * (2/49), W_LAST = 2 - W_FIRST, batch_step = (W_FIRST-W_LAST)/(B-1)
#define EPOCH_STEP (2.0 / 49.0)
#define W_FIRST_D  (2.0 - 10.0 * EPOCH_STEP)   /* ~1.5918367346938775 */
#define W_LAST_D   (2.0 - W_FIRST_D)
#define BATCH_STEP_D ((W_FIRST_D - W_LAST_D) / (double)(B_N - 1))

// Sortable keys: (float_bits << 12) | row_index.
// difficulty > 0 always, so the raw IEEE bit pattern is order-preserving.
// Low 12 bits = index -> exact stable-argsort tie-break in one u64 '<'.
__device__ __align__(16) unsigned long long g_keys[B_N];

// ---------------------------------------------------------------------------
// Kernel 1: difficulty[i] = 0.5*loss[i] + 0.5*||gradients[i,:]||_2
// One block per row, 256 threads, fully unrolled streaming float4 loads with
// 4 independent accumulators (short FFMA chains -> loads front-batch).
// Writes difficulty to out[1+i] AND the sortable key to g_keys[i].
// Block 0 zeroes the weighted-loss accumulator out[0].
// ---------------------------------------------------------------------------
__global__ __launch_bounds__(256) void difficulty_kernel(
    const float* __restrict__ loss,
    const float4* __restrict__ grad,       // [B, D/4]
    float* __restrict__ out)               // out[0]=acc, out[1..B]=difficulty
{
    const int row = blockIdx.x;
    const int tid = threadIdx.x;

    if (row == 0 && tid == 0) out[0] = 0.0f;   // reset accumulator (graph replay safe)

    const float4* __restrict__ g = grad + (size_t)row * (D_N / 4);

    float s0 = 0.0f, s1 = 0.0f, s2 = 0.0f, s3 = 0.0f;
#pragma unroll
    for (int it = 0; it < 4; it++) {
        // 4 independent streaming LDG.128 per unrolled step, 4 accumulators
        float4 a = __ldcs(&g[tid + (it * 4 + 0) * 256]);
        float4 b = __ldcs(&g[tid + (it * 4 + 1) * 256]);
        float4 c = __ldcs(&g[tid + (it * 4 + 2) * 256]);
        float4 d = __ldcs(&g[tid + (it * 4 + 3) * 256]);
        s0 = fmaf(a.x, a.x, s0); s0 = fmaf(a.y, a.y, s0);
        s0 = fmaf(a.z, a.z, s0); s0 = fmaf(a.w, a.w, s0);
        s1 = fmaf(b.x, b.x, s1); s1 = fmaf(b.y, b.y, s1);
        s1 = fmaf(b.z, b.z, s1); s1 = fmaf(b.w, b.w, s1);
        s2 = fmaf(c.x, c.x, s2); s2 = fmaf(c.y, c.y, s2);
        s2 = fmaf(c.z, c.z, s2); s2 = fmaf(c.w, c.w, s2);
        s3 = fmaf(d.x, d.x, s3); s3 = fmaf(d.y, d.y, s3);
        s3 = fmaf(d.z, d.z, s3); s3 = fmaf(d.w, d.w, s3);
    }
    float s = (s0 + s1) + (s2 + s3);

    // warp reduce
#pragma unroll
    for (int off = 16; off > 0; off >>= 1)
        s += __shfl_xor_sync(0xFFFFFFFFu, s, off);

    __shared__ float warp_sums[8];
    if ((tid & 31) == 0) warp_sums[tid >> 5] = s;
    __syncthreads();

    if (tid == 0) {
        float tot = 0.0f;
#pragma unroll
        for (int w = 0; w < 8; w++) tot += warp_sums[w];
        float d = 0.5f * loss[row] + 0.5f * sqrtf(tot);
        out[1 + row] = d;
        g_keys[row] = ((unsigned long long)__float_as_uint(d) << 12) | (unsigned)row;
    }
}

// ---------------------------------------------------------------------------
// Kernel 2 (R3-proven shape): counting rank + weighted loss accumulation.
// Each block owns 4 consecutive i's; 128 threads scan all B keys as uint4
// (2 u64 keys per 16B load) in a rolling loop, each load reused 4x.
// rank(i) = #{ key_j < key_i }  (exact stable-argsort rank via packed index)
// One atomicAdd per block into out[0].
// ---------------------------------------------------------------------------
#define IPB 4   // i's per block

__global__ __launch_bounds__(128) void rank_weight_kernel(
    const float* __restrict__ loss,
    float* __restrict__ out)
{
    const int i0  = blockIdx.x * IPB;
    const int tid = threadIdx.x;

    unsigned long long ki[IPB];
#pragma unroll
    for (int k = 0; k < IPB; k++) ki[k] = g_keys[i0 + k];

    int cnt[IPB] = {0, 0, 0, 0};

    const uint4* __restrict__ keys4 = (const uint4*)g_keys;  // 2 keys per uint4

#pragma unroll 4
    for (int p = tid; p < B_N / 2; p += 128) {
        uint4 v = keys4[p];
        unsigned long long k0 = ((unsigned long long)v.y << 32) | v.x;
        unsigned long long k1 = ((unsigned long long)v.w << 32) | v.z;
#pragma unroll
        for (int k = 0; k < IPB; k++) {
            cnt[k] += (k0 < ki[k]);
            cnt[k] += (k1 < ki[k]);
        }
    }

    // warp reduce all 4 counters
#pragma unroll
    for (int off = 16; off > 0; off >>= 1) {
#pragma unroll
        for (int k = 0; k < IPB; k++)
            cnt[k] += __shfl_xor_sync(0xFFFFFFFFu, cnt[k], off);
    }

    __shared__ int warp_cnt[4][IPB];
    if ((tid & 31) == 0) {
#pragma unroll
        for (int k = 0; k < IPB; k++)
            warp_cnt[tid >> 5][k] = cnt[k];
    }
    __syncthreads();

    if (tid == 0) {
        float contrib = 0.0f;
#pragma unroll
        for (int k = 0; k < IPB; k++) {
            int rank = warp_cnt[0][k] + warp_cnt[1][k] + warp_cnt[2][k] + warp_cnt[3][k];
            float w = (float)(W_FIRST_D - BATCH_STEP_D * (double)rank);
            contrib += __ldg(&loss[i0 + k]) * w;
        }
        atomicAdd(&out[0], contrib * (1.0f / (float)B_N));
    }
}

// ---------------------------------------------------------------------------
extern "C" void kernel_launch(void* const* d_in, const int* in_sizes, int n_in,
                              void* d_out, int out_size)
{
    const float*  loss = (const float*)d_in[0];
    const float4* grad = (const float4*)d_in[1];
    float* out = (float*)d_out;

    difficulty_kernel<<<B_N, 256>>>(loss, grad, out);
    rank_weight_kernel<<<B_N / IPB, 128>>>(loss, out);
}

// round 7
// speedup vs baseline: 1.0484x; 1.0061x over previous
#include <cuda_runtime.h>
#include <math.h>
#include <stdint.h>

#define B_N 4096
#define D_N 16384

// W_FIRST = 2 - 10 * (2/49), W_LAST = 2 - W_FIRST, batch_step = (W_FIRST-W_LAST)/(B-1)
#define EPOCH_STEP (2.0 / 49.0)
#define W_FIRST_D  (2.0 - 10.0 * EPOCH_STEP)   /* ~1.5918367346938775 */
#define W_LAST_D   (2.0 - W_FIRST_D)
#define BATCH_STEP_D ((W_FIRST_D - W_LAST_D) / (double)(B_N - 1))

// Sortable keys: (float_bits << 12) | row_index.
// difficulty > 0 always, so the raw IEEE bit pattern is order-preserving.
// Low 12 bits = index -> exact stable-argsort tie-break in one u64 '<'.
__device__ __align__(16) unsigned long long g_keys[B_N];

// ---------------------------------------------------------------------------
// Kernel 1: difficulty[i] = 0.5*loss[i] + 0.5*||gradients[i,:]||_2
// One block per row, 256 threads, streaming float4 loads, 4 accumulators.
// (R4-proven shape: 39.4us, ~6.8 TB/s)
// ---------------------------------------------------------------------------
__global__ __launch_bounds__(256) void difficulty_kernel(
    const float* __restrict__ loss,
    const float4* __restrict__ grad,       // [B, D/4]
    float* __restrict__ out)               // out[0]=acc, out[1..B]=difficulty
{
    const int row = blockIdx.x;
    const int tid = threadIdx.x;

    if (row == 0 && tid == 0) out[0] = 0.0f;   // reset accumulator (graph replay safe)

    const float4* __restrict__ g = grad + (size_t)row * (D_N / 4);

    float s0 = 0.0f, s1 = 0.0f, s2 = 0.0f, s3 = 0.0f;
#pragma unroll
    for (int it = 0; it < 4; it++) {
        float4 a = __ldcs(&g[tid + (it * 4 + 0) * 256]);
        float4 b = __ldcs(&g[tid + (it * 4 + 1) * 256]);
        float4 c = __ldcs(&g[tid + (it * 4 + 2) * 256]);
        float4 d = __ldcs(&g[tid + (it * 4 + 3) * 256]);
        s0 = fmaf(a.x, a.x, s0); s0 = fmaf(a.y, a.y, s0);
        s0 = fmaf(a.z, a.z, s0); s0 = fmaf(a.w, a.w, s0);
        s1 = fmaf(b.x, b.x, s1); s1 = fmaf(b.y, b.y, s1);
        s1 = fmaf(b.z, b.z, s1); s1 = fmaf(b.w, b.w, s1);
        s2 = fmaf(c.x, c.x, s2); s2 = fmaf(c.y, c.y, s2);
        s2 = fmaf(c.z, c.z, s2); s2 = fmaf(c.w, c.w, s2);
        s3 = fmaf(d.x, d.x, s3); s3 = fmaf(d.y, d.y, s3);
        s3 = fmaf(d.z, d.z, s3); s3 = fmaf(d.w, d.w, s3);
    }
    float s = (s0 + s1) + (s2 + s3);

    // warp reduce
#pragma unroll
    for (int off = 16; off > 0; off >>= 1)
        s += __shfl_xor_sync(0xFFFFFFFFu, s, off);

    __shared__ float warp_sums[8];
    if ((tid & 31) == 0) warp_sums[tid >> 5] = s;
    __syncthreads();

    if (tid == 0) {
        float tot = 0.0f;
#pragma unroll
        for (int w = 0; w < 8; w++) tot += warp_sums[w];
        float d = 0.5f * loss[row] + 0.5f * sqrtf(tot);
        out[1 + row] = d;
        g_keys[row] = ((unsigned long long)__float_as_uint(d) << 12) | (unsigned)row;
    }
}

// ---------------------------------------------------------------------------
// Kernel 2: counting rank + weighted loss accumulation.
// Each block owns 8 consecutive i's; 128 threads scan all B keys as uint4
// (2 u64 keys per 16B load) in a rolling loop; each load reused 8x
// (16 compares -> load latency hidden by its own compare work).
// rank(i) = #{ key_j < key_i }  (exact stable-argsort rank via packed index)
// One atomicAdd per block into out[0].
// ---------------------------------------------------------------------------
#define IPB 8   // i's per block

__global__ __launch_bounds__(128) void rank_weight_kernel(
    const float* __restrict__ loss,
    float* __restrict__ out)
{
    const int i0  = blockIdx.x * IPB;
    const int tid = threadIdx.x;

    unsigned long long ki[IPB];
#pragma unroll
    for (int k = 0; k < IPB; k++) ki[k] = g_keys[i0 + k];

    int cnt[IPB];
#pragma unroll
    for (int k = 0; k < IPB; k++) cnt[k] = 0;

    const uint4* __restrict__ keys4 = (const uint4*)g_keys;  // 2 keys per uint4

#pragma unroll 4
    for (int p = tid; p < B_N / 2; p += 128) {
        uint4 v = keys4[p];
        unsigned long long k0 = ((unsigned long long)v.y << 32) | v.x;
        unsigned long long k1 = ((unsigned long long)v.w << 32) | v.z;
#pragma unroll
        for (int k = 0; k < IPB; k++) {
            cnt[k] += (k0 < ki[k]);
            cnt[k] += (k1 < ki[k]);
        }
    }

    // warp reduce all counters
#pragma unroll
    for (int off = 16; off > 0; off >>= 1) {
#pragma unroll
        for (int k = 0; k < IPB; k++)
            cnt[k] += __shfl_xor_sync(0xFFFFFFFFu, cnt[k], off);
    }

    __shared__ int warp_cnt[4][IPB];
    if ((tid & 31) == 0) {
#pragma unroll
        for (int k = 0; k < IPB; k++)
            warp_cnt[tid >> 5][k] = cnt[k];
    }
    __syncthreads();

    if (tid == 0) {
        float contrib = 0.0f;
#pragma unroll
        for (int k = 0; k < IPB; k++) {
            int rank = warp_cnt[0][k] + warp_cnt[1][k] + warp_cnt[2][k] + warp_cnt[3][k];
            float w = (float)(W_FIRST_D - BATCH_STEP_D * (double)rank);
            contrib += __ldg(&loss[i0 + k]) * w;
        }
        atomicAdd(&out[0], contrib * (1.0f / (float)B_N));
    }
}

// ---------------------------------------------------------------------------
extern "C" void kernel_launch(void* const* d_in, const int* in_sizes, int n_in,
                              void* d_out, int out_size)
{
    const float*  loss = (const float*)d_in[0];
    const float4* grad = (const float4*)d_in[1];
    float* out = (float*)d_out;

    difficulty_kernel<<<B_N, 256>>>(loss, grad, out);
    rank_weight_kernel<<<B_N / IPB, 128>>>(loss, out);
}

// round 8
// speedup vs baseline: 1.0555x; 1.0068x over previous
#include <cuda_runtime.h>
#include <math.h>
#include <stdint.h>

#define B_N 4096
#define D_N 16384

// W_FIRST = 2 - 10 * (2/49), W_LAST = 2 - W_FIRST, batch_step = (W_FIRST-W_LAST)/(B-1)
#define EPOCH_STEP (2.0 / 49.0)
#define W_FIRST_D  (2.0 - 10.0 * EPOCH_STEP)   /* ~1.5918367346938775 */
#define W_LAST_D   (2.0 - W_FIRST_D)
#define BATCH_STEP_D ((W_FIRST_D - W_LAST_D) / (double)(B_N - 1))

// Sortable u32 keys: raw IEEE bits of difficulty (always > 0, so bit pattern
// is order-preserving). Ties (prob ~B^2*2^-32) cost ~1.7e-7 relative error,
// 4 orders of magnitude under the 1e-3 threshold -> strict '<' count is enough.
__device__ __align__(16) unsigned int g_keys[B_N];

// ---------------------------------------------------------------------------
// Kernel 1: difficulty[i] = 0.5*loss[i] + 0.5*||gradients[i,:]||_2
// One block per row, 256 threads, streaming float4 loads, 4 accumulators.
// (Proven shape: ~38.6us, ~6.9 TB/s)
// ---------------------------------------------------------------------------
__global__ __launch_bounds__(256) void difficulty_kernel(
    const float* __restrict__ loss,
    const float4* __restrict__ grad,       // [B, D/4]
    float* __restrict__ out)               // out[0]=acc, out[1..B]=difficulty
{
    const int row = blockIdx.x;
    const int tid = threadIdx.x;

    if (row == 0 && tid == 0) out[0] = 0.0f;   // reset accumulator (graph replay safe)

    const float4* __restrict__ g = grad + (size_t)row * (D_N / 4);

    float s0 = 0.0f, s1 = 0.0f, s2 = 0.0f, s3 = 0.0f;
#pragma unroll
    for (int it = 0; it < 4; it++) {
        float4 a = __ldcs(&g[tid + (it * 4 + 0) * 256]);
        float4 b = __ldcs(&g[tid + (it * 4 + 1) * 256]);
        float4 c = __ldcs(&g[tid + (it * 4 + 2) * 256]);
        float4 d = __ldcs(&g[tid + (it * 4 + 3) * 256]);
        s0 = fmaf(a.x, a.x, s0); s0 = fmaf(a.y, a.y, s0);
        s0 = fmaf(a.z, a.z, s0); s0 = fmaf(a.w, a.w, s0);
        s1 = fmaf(b.x, b.x, s1); s1 = fmaf(b.y, b.y, s1);
        s1 = fmaf(b.z, b.z, s1); s1 = fmaf(b.w, b.w, s1);
        s2 = fmaf(c.x, c.x, s2); s2 = fmaf(c.y, c.y, s2);
        s2 = fmaf(c.z, c.z, s2); s2 = fmaf(c.w, c.w, s2);
        s3 = fmaf(d.x, d.x, s3); s3 = fmaf(d.y, d.y, s3);
        s3 = fmaf(d.z, d.z, s3); s3 = fmaf(d.w, d.w, s3);
    }
    float s = (s0 + s1) + (s2 + s3);

    // warp reduce
#pragma unroll
    for (int off = 16; off > 0; off >>= 1)
        s += __shfl_xor_sync(0xFFFFFFFFu, s, off);

    __shared__ float warp_sums[8];
    if ((tid & 31) == 0) warp_sums[tid >> 5] = s;
    __syncthreads();

    if (tid == 0) {
        float tot = 0.0f;
#pragma unroll
        for (int w = 0; w < 8; w++) tot += warp_sums[w];
        float d = 0.5f * loss[row] + 0.5f * sqrtf(tot);
        out[1 + row] = d;
        g_keys[row] = __float_as_uint(d);
    }
}

// ---------------------------------------------------------------------------
// Kernel 2: counting rank + weighted loss accumulation (u32 keys).
// Each block owns 4 consecutive i's; 128 threads scan all B keys as uint4
// (4 u32 keys per 16B load) in a rolling loop; each load feeds 16 compares
// at 2 SASS instr each (ISETP.LT.U32 + predicated add).
// rank(i) = #{ key_j < key_i }
// One atomicAdd per block into out[0].
// ---------------------------------------------------------------------------
#define IPB 4   // i's per block

__global__ __launch_bounds__(128) void rank_weight_kernel(
    const float* __restrict__ loss,
    float* __restrict__ out)
{
    const int i0  = blockIdx.x * IPB;
    const int tid = threadIdx.x;

    unsigned int ki[IPB];
#pragma unroll
    for (int k = 0; k < IPB; k++) ki[k] = g_keys[i0 + k];

    int cnt[IPB] = {0, 0, 0, 0};

    const uint4* __restrict__ keys4 = (const uint4*)g_keys;  // 4 keys per uint4

#pragma unroll 4
    for (int p = tid; p < B_N / 4; p += 128) {
        uint4 v = keys4[p];
#pragma unroll
        for (int k = 0; k < IPB; k++) {
            cnt[k] += (v.x < ki[k]);
            cnt[k] += (v.y < ki[k]);
            cnt[k] += (v.z < ki[k]);
            cnt[k] += (v.w < ki[k]);
        }
    }

    // warp reduce all 4 counters
#pragma unroll
    for (int off = 16; off > 0; off >>= 1) {
#pragma unroll
        for (int k = 0; k < IPB; k++)
            cnt[k] += __shfl_xor_sync(0xFFFFFFFFu, cnt[k], off);
    }

    __shared__ int warp_cnt[4][IPB];
    if ((tid & 31) == 0) {
#pragma unroll
        for (int k = 0; k < IPB; k++)
            warp_cnt[tid >> 5][k] = cnt[k];
    }
    __syncthreads();

    if (tid == 0) {
        float contrib = 0.0f;
#pragma unroll
        for (int k = 0; k < IPB; k++) {
            int rank = warp_cnt[0][k] + warp_cnt[1][k] + warp_cnt[2][k] + warp_cnt[3][k];
            float w = (float)(W_FIRST_D - BATCH_STEP_D * (double)rank);
            contrib += __ldg(&loss[i0 + k]) * w;
        }
        atomicAdd(&out[0], contrib * (1.0f / (float)B_N));
    }
}

// ---------------------------------------------------------------------------
extern "C" void kernel_launch(void* const* d_in, const int* in_sizes, int n_in,
                              void* d_out, int out_size)
{
    const float*  loss = (const float*)d_in[0];
    const float4* grad = (const float4*)d_in[1];
    float* out = (float*)d_out;

    difficulty_kernel<<<B_N, 256>>>(loss, grad, out);
    rank_weight_kernel<<<B_N / IPB, 128>>>(loss, out);
}